// round 2
// baseline (speedup 1.0000x reference)
#include <cuda_runtime.h>
#include <cuda_bf16.h>
#include <cstdint>
#include <cstddef>

#define BB 2
#define TT 2048
#define CC 1024
#define HH 16
#define HD 64
#define MTOT (BB*TT)

#define DINLINE __device__ __forceinline__

// ---------------- scratch (__device__ globals; no cudaMalloc allowed) ------
__device__ float g_hln [MTOT*CC];
__device__ float g_qkv [MTOT*3*CC];
__device__ float g_yatt[MTOT*CC];
__device__ float g_h2  [MTOT*CC];
__device__ float g_mact[(size_t)MTOT*4*CC];
__device__ float g_wq  [3*CC*CC];
__device__ float g_wap [CC*CC];
__device__ float g_wfc [4*CC*CC];
__device__ float g_wpr [CC*4*CC];
__device__ float g_entp[1024];

// ---------------- helpers --------------------------------------------------
DINLINE uint32_t smem_u32(const void* p){ return (uint32_t)__cvta_generic_to_shared(p); }
DINLINE void cp_async16(const void* s, const void* g){
    asm volatile("cp.async.cg.shared.global [%0], [%1], 16;\n" :: "r"(smem_u32(s)), "l"(g));
}
DINLINE void cp_commit(){ asm volatile("cp.async.commit_group;\n"); }
DINLINE float rna_tf32(float x){
    uint32_t u; asm("cvt.rna.tf32.f32 %0, %1;" : "=r"(u) : "f"(x));
    return __uint_as_float(u);
}
DINLINE uint32_t pack_bf16(float lo, float hi){
    __nv_bfloat162 t = __floats2bfloat162_rn(lo, hi);
    return *reinterpret_cast<uint32_t*>(&t);
}
DINLINE void mma_tf32(float* d, const uint32_t* a, uint32_t b0, uint32_t b1){
    asm volatile("mma.sync.aligned.m16n8k8.row.col.f32.tf32.tf32.f32 "
        "{%0,%1,%2,%3},{%4,%5,%6,%7},{%8,%9},{%0,%1,%2,%3};\n"
        : "+f"(d[0]),"+f"(d[1]),"+f"(d[2]),"+f"(d[3])
        : "r"(a[0]),"r"(a[1]),"r"(a[2]),"r"(a[3]),"r"(b0),"r"(b1));
}
DINLINE void mma_bf16(float* d, uint32_t a0,uint32_t a1,uint32_t a2,uint32_t a3,
                      uint32_t b0, uint32_t b1){
    asm volatile("mma.sync.aligned.m16n8k16.row.col.f32.bf16.bf16.f32 "
        "{%0,%1,%2,%3},{%4,%5,%6,%7},{%8,%9},{%0,%1,%2,%3};\n"
        : "+f"(d[0]),"+f"(d[1]),"+f"(d[2]),"+f"(d[3])
        : "r"(a0),"r"(a1),"r"(a2),"r"(a3),"r"(b0),"r"(b1));
}
DINLINE float gelu_tanh(float v){
    float u = 0.7978845608028654f * (v + 0.044715f * v * v * v);
    return 0.5f * v * (1.0f + tanhf(u));
}

// ---------------- weight prep: round-to-nearest tf32 -----------------------
__global__ void rna_copy4(const float* __restrict__ in, float* __restrict__ out, int n4){
    int i = blockIdx.x * blockDim.x + threadIdx.x;
    int stride = gridDim.x * blockDim.x;
    for (; i < n4; i += stride){
        float4 v = ((const float4*)in)[i];
        v.x = rna_tf32(v.x); v.y = rna_tf32(v.y);
        v.z = rna_tf32(v.z); v.w = rna_tf32(v.w);
        ((float4*)out)[i] = v;
    }
}

// ---------------- LayerNorm (row/block, C=1024, rna output) ----------------
__global__ __launch_bounds__(256) void ln_kernel(
    const float* __restrict__ x, const float* __restrict__ w,
    const float* __restrict__ b, float* __restrict__ out)
{
    __shared__ float sS[8], sQ[8];
    __shared__ float sMean, sRstd;
    const int row = blockIdx.x, tid = threadIdx.x;
    float4 xv = *(const float4*)(x + (size_t)row * CC + tid * 4);
    float s = xv.x + xv.y + xv.z + xv.w;
    float q = xv.x*xv.x + xv.y*xv.y + xv.z*xv.z + xv.w*xv.w;
    #pragma unroll
    for (int o = 16; o; o >>= 1){
        s += __shfl_xor_sync(0xffffffffu, s, o);
        q += __shfl_xor_sync(0xffffffffu, q, o);
    }
    if ((tid & 31) == 0){ sS[tid >> 5] = s; sQ[tid >> 5] = q; }
    __syncthreads();
    if (tid == 0){
        float S = 0.f, Q = 0.f;
        #pragma unroll
        for (int i = 0; i < 8; i++){ S += sS[i]; Q += sQ[i]; }
        float mean = S * (1.0f / CC);
        sMean = mean; sRstd = rsqrtf(Q * (1.0f / CC) - mean * mean + 1e-5f);
    }
    __syncthreads();
    const float mean = sMean, r = sRstd;
    float4 wv = *(const float4*)(w + tid * 4);
    float4 bv = *(const float4*)(b + tid * 4);
    float4 ov;
    ov.x = rna_tf32((xv.x - mean) * r * wv.x + bv.x);
    ov.y = rna_tf32((xv.y - mean) * r * wv.y + bv.y);
    ov.z = rna_tf32((xv.z - mean) * r * wv.z + bv.z);
    ov.w = rna_tf32((xv.w - mean) * r * wv.w + bv.w);
    *(float4*)(out + (size_t)row * CC + tid * 4) = ov;
}

// ---------------- TF32 GEMM: out = epi(A[M,K] @ W[N,K]^T + bias) -----------
#define EPI_PLAIN 0
#define EPI_RES   1
#define EPI_GELU  2
#define GBM 128
#define GBN 128
#define GBK 16
#define GPAD 4

template<int EPI>
__global__ __launch_bounds__(256, 2) void gemm_tf32_kernel(
    const float* __restrict__ A, const float* __restrict__ W,
    const float* __restrict__ bias, const float* __restrict__ res,
    float* __restrict__ out, int M, int N, int K)
{
    __shared__ alignas(16) float As[2][GBM][GBK + GPAD];
    __shared__ alignas(16) float Bs[2][GBN][GBK + GPAD];
    const int tid  = threadIdx.x;
    const int bm   = blockIdx.y * GBM, bn = blockIdx.x * GBN;
    const int warp = tid >> 5, lane = tid & 31, g = lane >> 2, tg = lane & 3;
    const int wm   = (warp & 3) * 32, wn = (warp >> 2) * 64;
    const int r0   = tid >> 2, c0 = (tid & 3) * 4;

    const float* Ag0 = A + (size_t)(bm + r0)      * K + c0;
    const float* Ag1 = A + (size_t)(bm + r0 + 64) * K + c0;
    const float* Wg0 = W + (size_t)(bn + r0)      * K + c0;
    const float* Wg1 = W + (size_t)(bn + r0 + 64) * K + c0;

    float acc[2][8][4];
    #pragma unroll
    for (int i = 0; i < 2; i++)
        #pragma unroll
        for (int j = 0; j < 8; j++){ acc[i][j][0]=0.f; acc[i][j][1]=0.f; acc[i][j][2]=0.f; acc[i][j][3]=0.f; }

    cp_async16(&As[0][r0][c0],      Ag0);
    cp_async16(&As[0][r0 + 64][c0], Ag1);
    cp_async16(&Bs[0][r0][c0],      Wg0);
    cp_async16(&Bs[0][r0 + 64][c0], Wg1);
    cp_commit();

    const int KT = K / GBK;
    for (int kt = 0; kt < KT; ++kt){
        const int st = kt & 1;
        if (kt + 1 < KT){
            const int ko = (kt + 1) * GBK;
            cp_async16(&As[st ^ 1][r0][c0],      Ag0 + ko);
            cp_async16(&As[st ^ 1][r0 + 64][c0], Ag1 + ko);
            cp_async16(&Bs[st ^ 1][r0][c0],      Wg0 + ko);
            cp_async16(&Bs[st ^ 1][r0 + 64][c0], Wg1 + ko);
            cp_commit();
            asm volatile("cp.async.wait_group 1;\n");
        } else {
            asm volatile("cp.async.wait_group 0;\n");
        }
        __syncthreads();
        #pragma unroll
        for (int ks = 0; ks < 2; ++ks){
            const int k0 = ks * 8;
            uint32_t a[2][4];
            #pragma unroll
            for (int mi = 0; mi < 2; mi++){
                const int rm = wm + mi * 16;
                a[mi][0] = __float_as_uint(As[st][rm + g    ][k0 + tg    ]);
                a[mi][1] = __float_as_uint(As[st][rm + g + 8][k0 + tg    ]);
                a[mi][2] = __float_as_uint(As[st][rm + g    ][k0 + tg + 4]);
                a[mi][3] = __float_as_uint(As[st][rm + g + 8][k0 + tg + 4]);
            }
            #pragma unroll
            for (int ni = 0; ni < 8; ni++){
                uint32_t b0 = __float_as_uint(Bs[st][wn + ni*8 + g][k0 + tg    ]);
                uint32_t b1 = __float_as_uint(Bs[st][wn + ni*8 + g][k0 + tg + 4]);
                mma_tf32(acc[0][ni], a[0], b0, b1);
                mma_tf32(acc[1][ni], a[1], b0, b1);
            }
        }
        __syncthreads();
    }

    #pragma unroll
    for (int mi = 0; mi < 2; mi++){
        const int m0 = bm + wm + mi * 16 + g;
        #pragma unroll
        for (int ni = 0; ni < 8; ni++){
            const int col = bn + wn + ni * 8 + tg * 2;
            const float bv0 = bias[col], bv1 = bias[col + 1];
            float v00 = acc[mi][ni][0] + bv0, v01 = acc[mi][ni][1] + bv1;
            float v10 = acc[mi][ni][2] + bv0, v11 = acc[mi][ni][3] + bv1;
            const size_t i0 = (size_t)m0 * N + col;
            const size_t i1 = (size_t)(m0 + 8) * N + col;
            if (EPI == EPI_RES){
                float2 r0v = *(const float2*)(res + i0);
                float2 r1v = *(const float2*)(res + i1);
                v00 += r0v.x; v01 += r0v.y; v10 += r1v.x; v11 += r1v.y;
            } else if (EPI == EPI_GELU){
                v00 = rna_tf32(gelu_tanh(v00)); v01 = rna_tf32(gelu_tanh(v01));
                v10 = rna_tf32(gelu_tanh(v10)); v11 = rna_tf32(gelu_tanh(v11));
            }
            *(float2*)(out + i0) = make_float2(v00, v01);
            *(float2*)(out + i1) = make_float2(v10, v11);
        }
    }
}

// ---------------- flash attention + streaming entropy ----------------------
// grid = (32 qtiles, 16 heads, 2 batch); 128 threads = 4 warps x 16 q-rows.
__global__ __launch_bounds__(128) void flash_kernel(
    const float* __restrict__ qkv, float* __restrict__ y, float* __restrict__ entp)
{
    __shared__ __nv_bfloat16 Qs[64][72];
    __shared__ __nv_bfloat16 Ks[64][72];
    __shared__ __nv_bfloat16 Vt[64][72];   // Vt[hd][kpos]
    __shared__ float Hrow[64];

    const int tid = threadIdx.x, warp = tid >> 5, lane = tid & 31;
    const int g = lane >> 2, tg = lane & 3;
    const int qt = blockIdx.x, h = blockIdx.y, b = blockIdx.z;
    const int qm = warp * 16;
    const size_t base = (size_t)b * TT * (3 * CC) + (size_t)h * HD;

    // load Q tile, scale by 1/sqrt(HD)=0.125 (exact), cvt to bf16
    #pragma unroll
    for (int it = 0; it < 8; ++it){
        const int i = tid + it * 128;
        const int r = i >> 4, c4 = (i & 15) * 4;
        float4 v = *(const float4*)(qkv + base + (size_t)(qt * 64 + r) * (3 * CC) + c4);
        __nv_bfloat16* d = &Qs[r][c4];
        d[0] = __float2bfloat16(v.x * 0.125f); d[1] = __float2bfloat16(v.y * 0.125f);
        d[2] = __float2bfloat16(v.z * 0.125f); d[3] = __float2bfloat16(v.w * 0.125f);
    }

    float mrow[2] = {-1e30f, -1e30f}, lrow[2] = {0.f, 0.f}, trow[2] = {0.f, 0.f};
    float o[8][4];
    #pragma unroll
    for (int nd = 0; nd < 8; nd++){ o[nd][0]=0.f; o[nd][1]=0.f; o[nd][2]=0.f; o[nd][3]=0.f; }

    for (int kt = 0; kt <= qt; ++kt){
        __syncthreads();
        // load K tile and V tile (transposed) for positions kt*64..+63
        #pragma unroll
        for (int it = 0; it < 8; ++it){
            const int i = tid + it * 128;
            const int r = i >> 4, c4 = (i & 15) * 4;
            const size_t rowoff = base + (size_t)(kt * 64 + r) * (3 * CC) + c4;
            float4 kv = *(const float4*)(qkv + rowoff + CC);
            __nv_bfloat16* d = &Ks[r][c4];
            d[0] = __float2bfloat16(kv.x); d[1] = __float2bfloat16(kv.y);
            d[2] = __float2bfloat16(kv.z); d[3] = __float2bfloat16(kv.w);
            float4 vv = *(const float4*)(qkv + rowoff + 2 * CC);
            Vt[c4    ][r] = __float2bfloat16(vv.x);
            Vt[c4 + 1][r] = __float2bfloat16(vv.y);
            Vt[c4 + 2][r] = __float2bfloat16(vv.z);
            Vt[c4 + 3][r] = __float2bfloat16(vv.w);
        }
        __syncthreads();

        // S = Qs @ Ks^T  (16 q-rows per warp x 64 kpos)
        float s[8][4];
        #pragma unroll
        for (int nt = 0; nt < 8; nt++){ s[nt][0]=0.f; s[nt][1]=0.f; s[nt][2]=0.f; s[nt][3]=0.f; }
        #pragma unroll
        for (int kd = 0; kd < 4; kd++){
            const int k0 = kd * 16;
            uint32_t a0 = *(const uint32_t*)&Qs[qm + g    ][k0 + tg * 2];
            uint32_t a1 = *(const uint32_t*)&Qs[qm + g + 8][k0 + tg * 2];
            uint32_t a2 = *(const uint32_t*)&Qs[qm + g    ][k0 + tg * 2 + 8];
            uint32_t a3 = *(const uint32_t*)&Qs[qm + g + 8][k0 + tg * 2 + 8];
            #pragma unroll
            for (int nt = 0; nt < 8; nt++){
                uint32_t b0 = *(const uint32_t*)&Ks[nt * 8 + g][k0 + tg * 2];
                uint32_t b1 = *(const uint32_t*)&Ks[nt * 8 + g][k0 + tg * 2 + 8];
                mma_bf16(s[nt], a0, a1, a2, a3, b0, b1);
            }
        }
        // causal mask on diagonal tile
        if (kt == qt){
            #pragma unroll
            for (int nt = 0; nt < 8; nt++){
                const int kc = nt * 8 + tg * 2;
                if (kc     > qm + g    ) s[nt][0] = -1e30f;
                if (kc + 1 > qm + g    ) s[nt][1] = -1e30f;
                if (kc     > qm + 8 + g) s[nt][2] = -1e30f;
                if (kc + 1 > qm + 8 + g) s[nt][3] = -1e30f;
            }
        }
        // online softmax with entropy accumulators
        float tm0 = -1e30f, tm1 = -1e30f;
        #pragma unroll
        for (int nt = 0; nt < 8; nt++){
            tm0 = fmaxf(tm0, fmaxf(s[nt][0], s[nt][1]));
            tm1 = fmaxf(tm1, fmaxf(s[nt][2], s[nt][3]));
        }
        #pragma unroll
        for (int o2 = 1; o2 <= 2; o2 <<= 1){
            tm0 = fmaxf(tm0, __shfl_xor_sync(0xffffffffu, tm0, o2));
            tm1 = fmaxf(tm1, __shfl_xor_sync(0xffffffffu, tm1, o2));
        }
        const float m0n = fmaxf(mrow[0], tm0), m1n = fmaxf(mrow[1], tm1);
        const float c0 = expf(mrow[0] - m0n),  c1 = expf(mrow[1] - m1n);
        float sp0 = 0.f, st0 = 0.f, sp1 = 0.f, st1 = 0.f;
        uint32_t pa[8], pb[8];
        #pragma unroll
        for (int nt = 0; nt < 8; nt++){
            float p0 = expf(s[nt][0] - m0n), p1 = expf(s[nt][1] - m0n);
            float p2 = expf(s[nt][2] - m1n), p3 = expf(s[nt][3] - m1n);
            sp0 += p0 + p1;  st0 += p0 * s[nt][0] + p1 * s[nt][1];
            sp1 += p2 + p3;  st1 += p2 * s[nt][2] + p3 * s[nt][3];
            pa[nt] = pack_bf16(p0, p1);
            pb[nt] = pack_bf16(p2, p3);
        }
        #pragma unroll
        for (int o2 = 1; o2 <= 2; o2 <<= 1){
            sp0 += __shfl_xor_sync(0xffffffffu, sp0, o2);
            st0 += __shfl_xor_sync(0xffffffffu, st0, o2);
            sp1 += __shfl_xor_sync(0xffffffffu, sp1, o2);
            st1 += __shfl_xor_sync(0xffffffffu, st1, o2);
        }
        lrow[0] = lrow[0] * c0 + sp0;  trow[0] = trow[0] * c0 + st0;  mrow[0] = m0n;
        lrow[1] = lrow[1] * c1 + sp1;  trow[1] = trow[1] * c1 + st1;  mrow[1] = m1n;
        #pragma unroll
        for (int nd = 0; nd < 8; nd++){
            o[nd][0] *= c0; o[nd][1] *= c0; o[nd][2] *= c1; o[nd][3] *= c1;
        }
        // O += P @ V   (A-frags come straight from S-accumulator layout)
        #pragma unroll
        for (int kc = 0; kc < 4; kc++){
            const uint32_t a0 = pa[2*kc], a1 = pb[2*kc], a2 = pa[2*kc+1], a3 = pb[2*kc+1];
            const int k0 = kc * 16;
            #pragma unroll
            for (int nd = 0; nd < 8; nd++){
                uint32_t b0 = *(const uint32_t*)&Vt[nd * 8 + g][k0 + tg * 2];
                uint32_t b1 = *(const uint32_t*)&Vt[nd * 8 + g][k0 + tg * 2 + 8];
                mma_bf16(o[nd], a0, a1, a2, a3, b0, b1);
            }
        }
    }

    // epilogue: y = O / l (rna for downstream tf32 GEMM), per-row entropy
    const float il0 = 1.0f / lrow[0], il1 = 1.0f / lrow[1];
    const int q0 = qt * 64 + qm + g, q1 = q0 + 8;
    #pragma unroll
    for (int nd = 0; nd < 8; nd++){
        const int col = h * HD + nd * 8 + tg * 2;
        float2 v0 = make_float2(rna_tf32(o[nd][0] * il0), rna_tf32(o[nd][1] * il0));
        float2 v1 = make_float2(rna_tf32(o[nd][2] * il1), rna_tf32(o[nd][3] * il1));
        *(float2*)(y + (size_t)(b * TT + q0) * CC + col) = v0;
        *(float2*)(y + (size_t)(b * TT + q1) * CC + col) = v1;
    }
    const float H0 = mrow[0] + logf(lrow[0]) - trow[0] * il0;
    const float H1 = mrow[1] + logf(lrow[1]) - trow[1] * il1;
    if (tg == 0){ Hrow[qm + g] = H0; Hrow[qm + 8 + g] = H1; }
    __syncthreads();
    if (tid == 0){
        float ssum = 0.f;
        #pragma unroll
        for (int i = 0; i < 64; i++) ssum += Hrow[i];
        entp[(b * HH + h) * 32 + qt] = ssum;
    }
}

// ---------------- entropy final reduce -------------------------------------
__global__ __launch_bounds__(256) void entropy_reduce(const float* __restrict__ entp,
                                                      float* __restrict__ out)
{
    __shared__ float sh[8];
    const int tid = threadIdx.x;
    float s = entp[tid] + entp[tid + 256] + entp[tid + 512] + entp[tid + 768];
    #pragma unroll
    for (int o = 16; o; o >>= 1) s += __shfl_xor_sync(0xffffffffu, s, o);
    if ((tid & 31) == 0) sh[tid >> 5] = s;
    __syncthreads();
    if (tid == 0){
        float t = 0.f;
        #pragma unroll
        for (int i = 0; i < 8; i++) t += sh[i];
        out[0] = t * (1.0f / (float)(BB * HH * TT));
    }
}

// ---------------- launch ---------------------------------------------------
extern "C" void kernel_launch(void* const* d_in, const int* in_sizes, int n_in,
                              void* d_out, int out_size)
{
    (void)in_sizes; (void)n_in;
    const float* x      = (const float*)d_in[0];
    const float* ln1_w  = (const float*)d_in[1];
    const float* ln1_b  = (const float*)d_in[2];
    const float* attn_w = (const float*)d_in[3];
    const float* attn_b = (const float*)d_in[4];
    const float* ap_w   = (const float*)d_in[5];
    const float* ap_b   = (const float*)d_in[6];
    const float* ln2_w  = (const float*)d_in[7];
    const float* ln2_b  = (const float*)d_in[8];
    const float* fc_w   = (const float*)d_in[9];
    const float* fc_b   = (const float*)d_in[10];
    const float* pr_w   = (const float*)d_in[11];
    const float* pr_b   = (const float*)d_in[12];
    float* out = (float*)d_out;
    float* ent_out = out + (out_size - 1);

    float *wq, *wap, *wfc, *wpr, *hln, *qkv, *yatt, *h2, *mact, *entp;
    cudaGetSymbolAddress((void**)&wq,   g_wq);
    cudaGetSymbolAddress((void**)&wap,  g_wap);
    cudaGetSymbolAddress((void**)&wfc,  g_wfc);
    cudaGetSymbolAddress((void**)&wpr,  g_wpr);
    cudaGetSymbolAddress((void**)&hln,  g_hln);
    cudaGetSymbolAddress((void**)&qkv,  g_qkv);
    cudaGetSymbolAddress((void**)&yatt, g_yatt);
    cudaGetSymbolAddress((void**)&h2,   g_h2);
    cudaGetSymbolAddress((void**)&mact, g_mact);
    cudaGetSymbolAddress((void**)&entp, g_entp);

    // 1) weights -> rna tf32
    rna_copy4<<<2048, 256>>>(attn_w, wq,  3*CC*CC/4);
    rna_copy4<<<1024, 256>>>(ap_w,   wap, CC*CC/4);
    rna_copy4<<<2048, 256>>>(fc_w,   wfc, 4*CC*CC/4);
    rna_copy4<<<2048, 256>>>(pr_w,   wpr, CC*4*CC/4);
    // 2) LN1
    ln_kernel<<<MTOT, 256>>>(x, ln1_w, ln1_b, hln);
    // 3) qkv = ln1 @ attn_w^T + attn_b        [4096 x 3072 x 1024]
    gemm_tf32_kernel<EPI_PLAIN><<<dim3(3*CC/GBN, MTOT/GBM), 256>>>(
        hln, wq, attn_b, nullptr, qkv, MTOT, 3*CC, CC);
    // 4) flash attention + entropy partials
    flash_kernel<<<dim3(TT/64, HH, BB), 128>>>(qkv, yatt, entp);
    // 5) entropy scalar
    entropy_reduce<<<1, 256>>>(entp, ent_out);
    // 6) x1 = x + yatt @ ap_w^T + ap_b        [4096 x 1024 x 1024]
    gemm_tf32_kernel<EPI_RES><<<dim3(CC/GBN, MTOT/GBM), 256>>>(
        yatt, wap, ap_b, x, out, MTOT, CC, CC);
    // 7) LN2
    ln_kernel<<<MTOT, 256>>>(out, ln2_w, ln2_b, h2);
    // 8) m = gelu(h2 @ fc_w^T + fc_b)         [4096 x 4096 x 1024]
    gemm_tf32_kernel<EPI_GELU><<<dim3(4*CC/GBN, MTOT/GBM), 256>>>(
        h2, wfc, fc_b, nullptr, mact, MTOT, 4*CC, CC);
    // 9) x2 = x1 + m @ pr_w^T + pr_b          [4096 x 1024 x 4096]
    gemm_tf32_kernel<EPI_RES><<<dim3(CC/GBN, MTOT/GBM), 256>>>(
        mact, wpr, pr_b, out, out, MTOT, CC, 4*CC);
}